// round 15
// baseline (speedup 1.0000x reference)
#include <cuda_runtime.h>
#include <cuda_fp16.h>
#include <math.h>

#define BB 2
#define SS 1024
#define DM 1024
#define NH 16
#define DH 64
#define MROWS (BB*SS)
#define MAXN 0.996f

__device__ float g_qkv[3][MROWS*DM];
__device__ float g_aux[3][MROWS*NH];        // per-(row,head) final ||y||^2
__device__ unsigned g_kfrag[32*16*4*512];   // K  fp16 mma-frag order
__device__ unsigned g_vfrag[32*16*4*512];   // gamma*V fp16 mma-frag order
__device__ float4   g_sck[32*1024];         // per (bh,key): {k2, 1/(1-k2), gm1, e^mask}
__device__ unsigned g_xh[MROWS*DM/2];       // fp16x2(X)   [m][k/2]
__device__ unsigned g_zhT[3][DM*DM/2];      // fp16x2(Z^T) [n][k/2]
__device__ float    g_rowsq[MROWS];         // ||x_row||^2
__device__ float    g_colpart[3][16][DM];   // per-ktile col-norm partials
__device__ float4   g_cols[3][DM];          // {2cosh(2r)/zn, 2zn, sinh(2r), 0}

__device__ __forceinline__ unsigned packh2(float lo, float hi) {
    __half2 h = __floats2half2_rn(lo, hi);
    return *(unsigned*)&h;
}
__device__ __forceinline__ void mma16(float* d, const unsigned* a, const unsigned* b) {
    asm volatile("mma.sync.aligned.m16n8k16.row.col.f32.f16.f16.f32 "
        "{%0,%1,%2,%3}, {%4,%5,%6,%7}, {%8,%9}, {%0,%1,%2,%3};"
        : "+f"(d[0]), "+f"(d[1]), "+f"(d[2]), "+f"(d[3])
        : "r"(a[0]), "r"(a[1]), "r"(a[2]), "r"(a[3]), "r"(b[0]), "r"(b[1]));
}
__device__ __forceinline__ void ldsm4(unsigned* r, unsigned addr) {
    asm volatile("ldmatrix.sync.aligned.m8n8.x4.shared.b16 {%0,%1,%2,%3}, [%4];"
        : "=r"(r[0]), "=r"(r[1]), "=r"(r[2]), "=r"(r[3]) : "r"(addr));
}
__device__ __forceinline__ float fsqrt_a(float x){float r;asm("sqrt.approx.f32 %0,%1;":"=f"(r):"f"(x));return r;}
__device__ __forceinline__ float frcp_a (float x){float r;asm("rcp.approx.f32 %0,%1;" :"=f"(r):"f"(x));return r;}
__device__ __forceinline__ float flg2_a (float x){float r;asm("lg2.approx.f32 %0,%1;" :"=f"(r):"f"(x));return r;}
__device__ __forceinline__ float fex2_a (float x){float r;asm("ex2.approx.f32 %0,%1;" :"=f"(r):"f"(x));return r;}
__device__ __forceinline__ void cp16(unsigned s, const void* g) {
    asm volatile("cp.async.ca.shared.global [%0], [%1], 16;" :: "r"(s), "l"(g));
}

// ---------------------------------------------------------------------------
// Kernel 0a: X -> fp16 + row norms
// ---------------------------------------------------------------------------
__global__ __launch_bounds__(256)
void xcvt_kernel(const float* __restrict__ X) {
    int row = blockIdx.x * 8 + (threadIdx.x >> 5), lane = threadIdx.x & 31;
    const float* xr = X + row * DM;
    unsigned* xo = g_xh + row * (DM / 2);
    float s = 0.f;
    #pragma unroll
    for (int i = 0; i < 8; i++) {
        float4 v = *(const float4*)&xr[(i * 32 + lane) * 4];
        s = fmaf(v.x, v.x, fmaf(v.y, v.y, fmaf(v.z, v.z, fmaf(v.w, v.w, s))));
        *(uint2*)&xo[(i * 32 + lane) * 2] = make_uint2(packh2(v.x, v.y), packh2(v.z, v.w));
    }
    #pragma unroll
    for (int off = 16; off > 0; off >>= 1) s += __shfl_xor_sync(0xffffffffu, s, off);
    if (lane == 0) g_rowsq[row] = s;
}

// ---------------------------------------------------------------------------
// Kernel 0b: Z -> fp16 TRANSPOSED ([n][k]) via 64x64 smem tiles + col partials
// ---------------------------------------------------------------------------
__global__ __launch_bounds__(256)
void ztrans_kernel(const float* __restrict__ qz, const float* __restrict__ kz,
                   const float* __restrict__ vz) {
    __shared__ float tile[64][65];
    __shared__ float redc[16][64];
    int which = blockIdx.z;
    int k0 = blockIdx.x * 64, n0 = blockIdx.y * 64;
    const float* Z = (which == 0) ? qz : (which == 1) ? kz : vz;
    int t = threadIdx.x;
    float cp0 = 0.f, cp1 = 0.f, cp2 = 0.f, cp3 = 0.f;
    #pragma unroll
    for (int j = 0; j < 4; j++) {
        int idx = t + j * 256;
        int r = idx >> 4, c4 = (idx & 15) * 4;
        float4 v = *(const float4*)&Z[(k0 + r) * DM + n0 + c4];
        tile[r][c4] = v.x; tile[r][c4 + 1] = v.y;
        tile[r][c4 + 2] = v.z; tile[r][c4 + 3] = v.w;
        cp0 = fmaf(v.x, v.x, cp0); cp1 = fmaf(v.y, v.y, cp1);
        cp2 = fmaf(v.z, v.z, cp2); cp3 = fmaf(v.w, v.w, cp3);
    }
    int cg = (t & 15) * 4;
    redc[t >> 4][cg] = cp0; redc[t >> 4][cg + 1] = cp1;
    redc[t >> 4][cg + 2] = cp2; redc[t >> 4][cg + 3] = cp3;
    __syncthreads();
    if (t < 64) {
        float s = 0.f;
        #pragma unroll
        for (int g = 0; g < 16; g++) s += redc[g][t];
        g_colpart[which][blockIdx.x][n0 + t] = s;
    }
    #pragma unroll
    for (int j = 0; j < 4; j++) {
        int idx = t + j * 256;
        int nr = idx >> 4, kc4 = (idx & 15) * 4;
        *(uint2*)&g_zhT[which][(n0 + nr) * (DM / 2) + (k0 + kc4) / 2] =
            make_uint2(packh2(tile[kc4][nr], tile[kc4 + 1][nr]),
                       packh2(tile[kc4 + 2][nr], tile[kc4 + 3][nr]));
    }
}

// ---------------------------------------------------------------------------
// Kernel 0c: finish column scalars (sum 16 partials)
// ---------------------------------------------------------------------------
__global__ __launch_bounds__(256)
void col_finish_kernel(const float* __restrict__ qr, const float* __restrict__ kr,
                       const float* __restrict__ vr) {
    int gid = blockIdx.x * 256 + threadIdx.x;   // 0..3071
    int which = gid >> 10, col = gid & 1023;
    const float* R = (which == 0) ? qr : (which == 1) ? kr : vr;
    float zs = 0.f;
    #pragma unroll
    for (int p = 0; p < 16; p++) zs += g_colpart[which][p][col];
    float zn = fmaxf(fsqrt_a(zs), 1e-15f);
    float rv = 2.0f * R[col];
    float e  = fex2_a(rv * 1.44269504f);
    float ie = frcp_a(e);
    g_cols[which][col] = make_float4((e + ie) * frcp_a(zn), 2.0f * zn, 0.5f * (e - ie), 0.f);
}

// ---------------------------------------------------------------------------
// Kernel 1: fp16 m16n8k16 GEMM, 512 threads (16 warps, 8x2 grid, 16x64 warp
// tile), cp.async 2-stage pipeline, ldmatrix loads, fused Poincare epilogue.
// occ: 2 blocks/SM -> 32 warps/SM (R13 had 16).
// ---------------------------------------------------------------------------
#define GEMM_STAGE (128*36)                    // uints per stage per operand
#define GEMM_SMEM_WORDS (4*GEMM_STAGE)
__global__ __launch_bounds__(512, 2)
void gemm_proj_kernel() {
    int which = blockIdx.z;
    const unsigned* Xh = g_xh;
    const unsigned* Zh = g_zhT[which];
    float* Cw = g_qkv[which];

    extern __shared__ unsigned gsm[];
    unsigned sbase = (unsigned)__cvta_generic_to_shared(gsm);
    unsigned sa = sbase, sb = sbase + 2 * GEMM_STAGE * 4;

    int t = threadIdx.x;
    int wid = t >> 5, lane = t & 31;
    int L2 = lane >> 2, L0 = lane & 3;
    int wm = wid >> 1, wn = wid & 1;     // 8 x 2 warp grid
    int m0 = blockIdx.x * 128, n0 = blockIdx.y * 128;

    // ldmatrix per-lane address components
    int mat = lane >> 3, lr = lane & 7;
    int a_row = (mat & 1) * 8 + lr;      // within 16-row warp tile
    int a_kof = (mat >> 1) * 4;
    int b_row = (mat >> 1) * 8 + lr;     // within 16 of the 64 warp cols
    int b_kof = (mat & 1) * 4;

    float acc[8][4] = {};

    // per-tile copy: 1024 x 16B per operand; 2 per thread each
#define G_PREFETCH(kc, sg) do {                                               \
        _Pragma("unroll")                                                     \
        for (int j_ = 0; j_ < 2; j_++) {                                      \
            int u_ = t + j_ * 512;                                            \
            int row_ = u_ >> 3, seg_ = u_ & 7;                                \
            unsigned off_ = (((unsigned)(sg) * 128 + row_) * 36 + seg_ * 4) * 4; \
            cp16(sa + off_, &Xh[(m0 + row_) * (DM/2) + (kc) * 32 + seg_ * 4]); \
            cp16(sb + off_, &Zh[(n0 + row_) * (DM/2) + (kc) * 32 + seg_ * 4]); \
        }                                                                     \
        asm volatile("cp.async.commit_group;");                               \
    } while (0)

    G_PREFETCH(0, 0);

    #pragma unroll 1
    for (int kt = 0; kt < 16; kt++) {
        int st = kt & 1;
        asm volatile("cp.async.wait_group 0;");
        __syncthreads();
        if (kt + 1 < 16) G_PREFETCH(kt + 1, st ^ 1);
        unsigned abase = sa + ((unsigned)(st * 128 + wm * 16 + a_row) * 36 + a_kof) * 4;
        unsigned bbase = sb + ((unsigned)(st * 128 + wn * 64 + b_row) * 36 + b_kof) * 4;
        #pragma unroll
        for (int s8 = 0; s8 < 4; s8++) {
            unsigned a[4];
            ldsm4(a, abase + (s8 * 8) * 4);
            #pragma unroll
            for (int p = 0; p < 4; p++) {
                unsigned b[4];
                ldsm4(b, bbase + ((p * 16) * 36 + s8 * 8) * 4);
                mma16(acc[p * 2],     a, &b[0]);
                mma16(acc[p * 2 + 1], a, &b[2]);
            }
        }
    }

    // ---- fused Poincare epilogue (scalars from L2-resident globals) ----
    int head = (n0 >> 6) + wn;
    #pragma unroll
    for (int hh = 0; hh < 2; hh++) {
        int rloc = wm * 16 + hh * 8 + L2;
        float cx2 = g_rowsq[m0 + rloc];
        float invden = frcp_a(fmaxf(1.0f - cx2, 1e-15f));
        float opc = 1.0f + cx2;
        float sq = 0.f;
        #pragma unroll
        for (int nt = 0; nt < 8; nt++) {
            int cl = wn * 64 + nt * 8 + 2 * L0;
            float4 cs0 = g_cols[which][n0 + cl];
            float4 cs1 = g_cols[which][n0 + cl + 1];
            #pragma unroll
            for (int u = 0; u < 2; u++) {
                float4 cs = u ? cs1 : cs0;
                float xz  = acc[nt][hh * 2 + u];
                float arg = fmaf(xz, cs.x, -opc * cs.z) * invden;
                float aa  = fabsf(arg);
                float A   = aa + fsqrt_a(fmaf(aa, aa, 1.0f));
                float tE  = fex2_a(cs.y * flg2_a(A));
                float y   = copysignf(0.5f * (tE - frcp_a(tE)), arg);
                acc[nt][hh * 2 + u] = y;
                sq = fmaf(y, y, sq);
            }
        }
        sq += __shfl_xor_sync(0xffffffffu, sq, 1);
        sq += __shfl_xor_sync(0xffffffffu, sq, 2);
        float n1  = fmaxf(sqrtf(sq), 1e-15f);
        float s1  = (n1 > MAXN) ? (MAXN / n1) : 1.0f;
        float n1c = n1 * s1;
        float f   = 1.0f / (1.0f + sqrtf(1.0f + n1c * n1c));
        float n2  = fmaxf(n1c * f, 1e-15f);
        float s2v = (n2 > MAXN) ? (MAXN / n2) : 1.0f;
        float hs  = s1 * f * s2v;
        float n3  = n2 * s2v;
        int grow = m0 + rloc;
        if (L0 == 0) g_aux[which][grow * NH + head] = n3 * n3;
        #pragma unroll
        for (int nt = 0; nt < 8; nt++) {
            int cl = wn * 64 + nt * 8 + 2 * L0;
            *(float2*)&Cw[grow * DM + n0 + cl] =
                make_float2(acc[nt][hh * 2] * hs, acc[nt][hh * 2 + 1] * hs);
        }
    }
}

// ---------------------------------------------------------------------------
// Kernel 2: one-shot fp16 fragment prep for K / gamma*V.
// ---------------------------------------------------------------------------
__global__ __launch_bounds__(256)
void frag_prep_kernel(const float* __restrict__ mask) {
    __shared__ float Ks[64][68];
    __shared__ float Vs[64][68];

    int bh = blockIdx.x, kt = blockIdx.y;
    int b = bh >> 4, h = bh & 15;
    int kj0 = kt * 64;
    int t = threadIdx.x, lane = t & 31;
    int L2 = lane >> 2, L0 = lane & 3;
    int w = t >> 5;
    int s = w & 3;
    bool isV = (w >= 4);

    const float* K = g_qkv[1];
    const float* V = g_qkv[2];

    #pragma unroll
    for (int j = 0; j < 4; j++) {
        int idx = t + j * 256;
        int row = idx >> 4, c4 = (idx & 15) * 4;
        int gr = b * SS + kj0 + row;
        *(float4*)&Ks[row][c4] = *(const float4*)&K[gr * DM + h * DH + c4];
        float v2 = g_aux[2][gr * NH + h];
        float gam = 2.0f * frcp_a(fmaxf(1.0f - v2, 1e-15f));
        float4 vv = *(const float4*)&V[gr * DM + h * DH + c4];
        *(float4*)&Vs[row][c4] = make_float4(vv.x * gam, vv.y * gam, vv.z * gam, vv.w * gam);
    }
    if (t < 64) {
        int gr = b * SS + kj0 + t;
        float k2 = g_aux[1][gr * NH + h];
        float v2 = g_aux[2][gr * NH + h];
        g_sck[bh * 1024 + kj0 + t] =
            make_float4(k2, frcp_a(fmaxf(1.0f - k2, 1e-15f)),
                        2.0f * frcp_a(fmaxf(1.0f - v2, 1e-15f)) - 1.0f,
                        __expf(mask[b * SS + kj0 + t]));
    }
    __syncthreads();

    unsigned wf[16];
    if (!isV) {
        #pragma unroll
        for (int nt = 0; nt < 8; nt++) {
            int c = nt * 8 + L2;
            wf[2*nt]   = packh2(Ks[c][s * 16 + 2 * L0],     Ks[c][s * 16 + 2 * L0 + 1]);
            wf[2*nt+1] = packh2(Ks[c][s * 16 + 2 * L0 + 8], Ks[c][s * 16 + 2 * L0 + 9]);
        }
    } else {
        #pragma unroll
        for (int nt = 0; nt < 8; nt++) {
            int d = nt * 8 + L2;
            wf[2*nt]   = packh2(Vs[s * 16 + 2 * L0][d],     Vs[s * 16 + 2 * L0 + 1][d]);
            wf[2*nt+1] = packh2(Vs[s * 16 + 2 * L0 + 8][d], Vs[s * 16 + 2 * L0 + 9][d]);
        }
    }
    unsigned base = (((unsigned)(bh * 16 + kt) * 4) + s) * 512 + lane * 4;
    unsigned* dst = isV ? g_vfrag : g_kfrag;
    #pragma unroll
    for (int i4 = 0; i4 < 4; i4++)
        *(uint4*)&dst[base + i4 * 128] = ((uint4*)wf)[i4];
}

// ---------------------------------------------------------------------------
// Kernel 3: flash-style hyperbolic attention, fp16 m16n8k16 (unchanged)
// ---------------------------------------------------------------------------
#define ATT_SMEM_WORDS (4096 + 128*34 + 8*64*4 + 128)
__global__ __launch_bounds__(256, 2)
void attn_kernel(float* __restrict__ out) {
    extern __shared__ unsigned smu[];
    unsigned* qf = smu;                                   // 4096: Q fp16 frags
    unsigned (*ps)[34] = (unsigned(*)[34])(smu + 4096);   // 128x34 P fp16x2
    float4* sws = (float4*)(smu + 4096 + 128*34);
    float* q2s  = (float*)(smu + 4096 + 128*34 + 8*64*4);

    int bh = blockIdx.x, qt = blockIdx.y;
    int b = bh >> 4, h = bh & 15;
    int t = threadIdx.x, wid = t >> 5, lane = t & 31;
    int L2 = lane >> 2, L0 = lane & 3;
    int qi0 = qt * 128;

    const float* Q = g_qkv[0];

    #pragma unroll
    for (int j = 0; j < 8; j++) {
        int idx = t + j * 256;
        int row = idx >> 4, c4 = (idx & 15) * 4;
        float4 v = *(const float4*)&Q[(b * SS + qi0 + row) * DM + h * DH + c4];
        int rb = row >> 4, rr = row & 15;
        int s  = c4 >> 4;
        int j0 = (c4 & 15) >> 1;
        int lane0 = (rr & 7) * 4 + (j0 & 3);
        int reg   = (rr >> 3) + 2 * (j0 >> 2);
        unsigned* qb = qf + (((rb * 4 + s) * 32 + lane0) * 4) + reg;
        qb[0] = packh2(v.x, v.y);
        qb[4] = packh2(v.z, v.w);
    }
    if (t < 128) q2s[t] = g_aux[0][(b * SS + qi0 + t) * NH + h];
    __syncthreads();

    int rA = wid * 16 + L2;
    float q2_0 = q2s[rA], q2_1 = q2s[rA + 8];
    float tiq0 = 2.0f * frcp_a(fmaxf(1.0f - q2_0, 1e-15f));
    float tiq1 = 2.0f * frcp_a(fmaxf(1.0f - q2_1, 1e-15f));

    float4* swsW = sws + wid * 64;
    const float4* sckB = g_sck + bh * 1024;

    float o[8][4] = {};
    float accd0 = 0.f, accd1 = 0.f;

    for (int kt = 0; kt < SS / 64; kt++) {
        int kj0 = kt * 64;
        size_t fb = (size_t)((unsigned)(bh * 16 + kt) * 4) * 512 + lane * 4;
        const unsigned* kfb = g_kfrag + fb;
        const unsigned* vfb = g_vfrag + fb;

        swsW[lane * 2]     = sckB[kj0 + lane * 2];
        swsW[lane * 2 + 1] = sckB[kj0 + lane * 2 + 1];
        __syncwarp();

        float s[8][4] = {};
        #pragma unroll
        for (int st = 0; st < 4; st++) {
            uint4 af = *(uint4*)&qf[((wid * 4 + st) * 32 + lane) * 4];
            unsigned a[4] = { af.x, af.y, af.z, af.w };
            unsigned kw[16];
            #pragma unroll
            for (int i4 = 0; i4 < 4; i4++)
                *(uint4*)&kw[i4 * 4] = *(const uint4*)&kfb[st * 512 + i4 * 128];
            #pragma unroll
            for (int nt = 0; nt < 8; nt++) mma16(s[nt], a, &kw[nt * 2]);
        }

        #pragma unroll
        for (int nt = 0; nt < 8; nt++) {
            int j0 = nt * 8 + 2 * L0;
            float4 c0 = swsW[j0], c1 = swsW[j0 + 1];
            float w[4];
            #pragma unroll
            for (int e = 0; e < 4; e++) {
                float q2v = (e < 2) ? q2_0 : q2_1;
                float cc  = ((e < 2) ? tiq0 : tiq1) * ((e & 1) ? c1.y : c0.y);
                float k2v = (e & 1) ? c1.x : c0.x;
                float emv = (e & 1) ? c1.w : c0.w;
                float num = fmaxf(fmaf(-2.0f, s[nt][e], q2v + k2v), 1e-15f);
                float tt  = num * cc;
                float sr  = fsqrt_a(tt * (tt + 2.0f));
                w[e] = __fdividef(emv, (1.0f + tt) + sr);
            }
            accd0 = fmaf(w[0], c0.z, fmaf(w[1], c1.z, accd0));
            accd1 = fmaf(w[2], c0.z, fmaf(w[3], c1.z, accd1));
            ps[rA][nt * 4 + L0]     = packh2(w[0], w[1]);
            ps[rA + 8][nt * 4 + L0] = packh2(w[2], w[3]);
        }
        __syncwarp();

        #pragma unroll
        for (int st = 0; st < 4; st++) {
            int kb = st * 8 + L0;
            unsigned a[4] = { ps[rA][kb], ps[rA + 8][kb], ps[rA][kb + 4], ps[rA + 8][kb + 4] };
            unsigned vw[16];
            #pragma unroll
            for (int i4 = 0; i4 < 4; i4++)
                *(uint4*)&vw[i4 * 4] = *(const uint4*)&vfb[st * 512 + i4 * 128];
            #pragma unroll
            for (int nt = 0; nt < 8; nt++) mma16(o[nt], a, &vw[nt * 2]);
        }
        __syncwarp();
    }

    accd0 += __shfl_xor_sync(0xffffffffu, accd0, 1);
    accd0 += __shfl_xor_sync(0xffffffffu, accd0, 2);
    accd1 += __shfl_xor_sync(0xffffffffu, accd1, 1);
    accd1 += __shfl_xor_sync(0xffffffffu, accd1, 2);
    #pragma unroll
    for (int rh = 0; rh < 2; rh++) {
        float accd = rh ? accd1 : accd0;
        float invd = 1.0f / fmaxf(accd, 1e-10f);
        float tm[8][2];
        float sq = 0.f;
        #pragma unroll
        for (int nt = 0; nt < 8; nt++) {
            tm[nt][0] = o[nt][rh * 2 + 0] * invd;
            tm[nt][1] = o[nt][rh * 2 + 1] * invd;
            sq += tm[nt][0] * tm[nt][0] + tm[nt][1] * tm[nt][1];
        }
        sq += __shfl_xor_sync(0xffffffffu, sq, 1);
        sq += __shfl_xor_sync(0xffffffffu, sq, 2);
        float f = 1.0f / (1.0f + sqrtf(fmaxf(1.0f - sq, 1e-15f)));
        float n = fmaxf(sqrtf(sq) * f, 1e-15f);
        float s2 = (n > MAXN) ? (MAXN / n) : 1.0f;
        float g = f * s2;
        int qrow = qi0 + rA + rh * 8;
        #pragma unroll
        for (int nt = 0; nt < 8; nt++) {
            *(float2*)&out[(b * SS + qrow) * DM + h * DH + nt * 8 + 2 * L0] =
                make_float2(tm[nt][0] * g, tm[nt][1] * g);
        }
    }
}

// ---------------------------------------------------------------------------
extern "C" void kernel_launch(void* const* d_in, const int* in_sizes, int n_in,
                              void* d_out, int out_size) {
    const float* hidden = (const float*)d_in[0];
    const float* amask  = (const float*)d_in[1];
    const float* qz = (const float*)d_in[2];
    const float* qr = (const float*)d_in[3];
    const float* kz = (const float*)d_in[4];
    const float* kr = (const float*)d_in[5];
    const float* vz = (const float*)d_in[6];
    const float* vr = (const float*)d_in[7];
    float* out = (float*)d_out;

    static bool attr_done = false;
    if (!attr_done) {
        cudaFuncSetAttribute(attn_kernel, cudaFuncAttributeMaxDynamicSharedMemorySize,
                             ATT_SMEM_WORDS * 4);
        cudaFuncSetAttribute(gemm_proj_kernel, cudaFuncAttributeMaxDynamicSharedMemorySize,
                             GEMM_SMEM_WORDS * 4);
        attr_done = true;
    }

    xcvt_kernel<<<256, 256>>>(hidden);
    ztrans_kernel<<<dim3(16, 16, 3), 256>>>(qz, kz, vz);
    col_finish_kernel<<<12, 256>>>(qr, kr, vr);
    gemm_proj_kernel<<<dim3(MROWS / 128, DM / 128, 3), 512, GEMM_SMEM_WORDS * 4>>>();
    frag_prep_kernel<<<dim3(32, 16), 256>>>(amask);
    attn_kernel<<<dim3(BB * NH, SS / 128), 256, ATT_SMEM_WORDS * 4>>>(out);
}

// round 16
// speedup vs baseline: 1.1881x; 1.1881x over previous
#include <cuda_runtime.h>
#include <cuda_fp16.h>
#include <math.h>

#define BB 2
#define SS 1024
#define DM 1024
#define NH 16
#define DH 64
#define MROWS (BB*SS)
#define MAXN 0.996f

__device__ float g_qkv[3][MROWS*DM];
__device__ float g_aux[3][MROWS*NH];        // per-(row,head) final ||y||^2
__device__ unsigned g_kfrag[32*16*4*512];   // K  fp16 mma-frag order
__device__ unsigned g_vfrag[32*16*4*512];   // gamma*V fp16 mma-frag order
__device__ float4   g_sck[32*1024];         // per (bh,key): {k2, 1/(1-k2), gm1, e^mask}
__device__ unsigned g_xh[MROWS*DM/2];       // fp16x2(X)   [m][k/2]
__device__ unsigned g_zhT[3][DM*DM/2];      // fp16x2(Z^T) [n][k/2]
__device__ float    g_rowsq[MROWS];         // ||x_row||^2
__device__ float    g_colpart[3][16][DM];   // per-ktile col-norm partials
__device__ float4   g_cols[3][DM];          // {2cosh(2r)/zn, 2zn, sinh(2r), 0}

__device__ __forceinline__ unsigned packh2(float lo, float hi) {
    __half2 h = __floats2half2_rn(lo, hi);
    return *(unsigned*)&h;
}
__device__ __forceinline__ void mma16(float* d, const unsigned* a, const unsigned* b) {
    asm volatile("mma.sync.aligned.m16n8k16.row.col.f32.f16.f16.f32 "
        "{%0,%1,%2,%3}, {%4,%5,%6,%7}, {%8,%9}, {%0,%1,%2,%3};"
        : "+f"(d[0]), "+f"(d[1]), "+f"(d[2]), "+f"(d[3])
        : "r"(a[0]), "r"(a[1]), "r"(a[2]), "r"(a[3]), "r"(b[0]), "r"(b[1]));
}
__device__ __forceinline__ void ldsm4(unsigned* r, unsigned addr) {
    asm volatile("ldmatrix.sync.aligned.m8n8.x4.shared.b16 {%0,%1,%2,%3}, [%4];"
        : "=r"(r[0]), "=r"(r[1]), "=r"(r[2]), "=r"(r[3]) : "r"(addr));
}
__device__ __forceinline__ float fsqrt_a(float x){float r;asm("sqrt.approx.f32 %0,%1;":"=f"(r):"f"(x));return r;}
__device__ __forceinline__ float frcp_a (float x){float r;asm("rcp.approx.f32 %0,%1;" :"=f"(r):"f"(x));return r;}
__device__ __forceinline__ float flg2_a (float x){float r;asm("lg2.approx.f32 %0,%1;" :"=f"(r):"f"(x));return r;}
__device__ __forceinline__ float fex2_a (float x){float r;asm("ex2.approx.f32 %0,%1;" :"=f"(r):"f"(x));return r;}
__device__ __forceinline__ void cp16(unsigned s, const void* g) {
    asm volatile("cp.async.ca.shared.global [%0], [%1], 16;" :: "r"(s), "l"(g));
}

// ---------------------------------------------------------------------------
// Kernel 0a: X -> fp16 + row norms
// ---------------------------------------------------------------------------
__global__ __launch_bounds__(256)
void xcvt_kernel(const float* __restrict__ X) {
    int row = blockIdx.x * 8 + (threadIdx.x >> 5), lane = threadIdx.x & 31;
    const float* xr = X + row * DM;
    unsigned* xo = g_xh + row * (DM / 2);
    float s = 0.f;
    #pragma unroll
    for (int i = 0; i < 8; i++) {
        float4 v = *(const float4*)&xr[(i * 32 + lane) * 4];
        s = fmaf(v.x, v.x, fmaf(v.y, v.y, fmaf(v.z, v.z, fmaf(v.w, v.w, s))));
        *(uint2*)&xo[(i * 32 + lane) * 2] = make_uint2(packh2(v.x, v.y), packh2(v.z, v.w));
    }
    #pragma unroll
    for (int off = 16; off > 0; off >>= 1) s += __shfl_xor_sync(0xffffffffu, s, off);
    if (lane == 0) g_rowsq[row] = s;
}

// ---------------------------------------------------------------------------
// Kernel 0b: Z -> fp16 TRANSPOSED ([n][k]) via 64x64 smem tiles + col partials
// ---------------------------------------------------------------------------
__global__ __launch_bounds__(256)
void ztrans_kernel(const float* __restrict__ qz, const float* __restrict__ kz,
                   const float* __restrict__ vz) {
    __shared__ float tile[64][65];
    __shared__ float redc[16][64];
    int which = blockIdx.z;
    int k0 = blockIdx.x * 64, n0 = blockIdx.y * 64;
    const float* Z = (which == 0) ? qz : (which == 1) ? kz : vz;
    int t = threadIdx.x;
    float cp0 = 0.f, cp1 = 0.f, cp2 = 0.f, cp3 = 0.f;
    #pragma unroll
    for (int j = 0; j < 4; j++) {
        int idx = t + j * 256;
        int r = idx >> 4, c4 = (idx & 15) * 4;
        float4 v = *(const float4*)&Z[(k0 + r) * DM + n0 + c4];
        tile[r][c4] = v.x; tile[r][c4 + 1] = v.y;
        tile[r][c4 + 2] = v.z; tile[r][c4 + 3] = v.w;
        cp0 = fmaf(v.x, v.x, cp0); cp1 = fmaf(v.y, v.y, cp1);
        cp2 = fmaf(v.z, v.z, cp2); cp3 = fmaf(v.w, v.w, cp3);
    }
    int cg = (t & 15) * 4;
    redc[t >> 4][cg] = cp0; redc[t >> 4][cg + 1] = cp1;
    redc[t >> 4][cg + 2] = cp2; redc[t >> 4][cg + 3] = cp3;
    __syncthreads();
    if (t < 64) {
        float s = 0.f;
        #pragma unroll
        for (int g = 0; g < 16; g++) s += redc[g][t];
        g_colpart[which][blockIdx.x][n0 + t] = s;
    }
    #pragma unroll
    for (int j = 0; j < 4; j++) {
        int idx = t + j * 256;
        int nr = idx >> 4, kc4 = (idx & 15) * 4;
        *(uint2*)&g_zhT[which][(n0 + nr) * (DM / 2) + (k0 + kc4) / 2] =
            make_uint2(packh2(tile[kc4][nr], tile[kc4 + 1][nr]),
                       packh2(tile[kc4 + 2][nr], tile[kc4 + 3][nr]));
    }
}

// ---------------------------------------------------------------------------
// Kernel 0c: finish column scalars (sum 16 partials)
// ---------------------------------------------------------------------------
__global__ __launch_bounds__(256)
void col_finish_kernel(const float* __restrict__ qr, const float* __restrict__ kr,
                       const float* __restrict__ vr) {
    int gid = blockIdx.x * 256 + threadIdx.x;   // 0..3071
    int which = gid >> 10, col = gid & 1023;
    const float* R = (which == 0) ? qr : (which == 1) ? kr : vr;
    float zs = 0.f;
    #pragma unroll
    for (int p = 0; p < 16; p++) zs += g_colpart[which][p][col];
    float zn = fmaxf(fsqrt_a(zs), 1e-15f);
    float rv = 2.0f * R[col];
    float e  = fex2_a(rv * 1.44269504f);
    float ie = frcp_a(e);
    g_cols[which][col] = make_float4((e + ie) * frcp_a(zn), 2.0f * zn, 0.5f * (e - ie), 0.f);
}

// ---------------------------------------------------------------------------
// Kernel 1: fp16 m16n8k16 GEMM (R13 proven: 256 thr, 32x64 warp tile,
// 2-stage cp.async, ldmatrix), fused Poincare epilogue.
// ---------------------------------------------------------------------------
#define GEMM_STAGE (128*36)                    // uints per stage per operand
#define GEMM_SMEM_WORDS (4*GEMM_STAGE)
__global__ __launch_bounds__(256, 2)
void gemm_proj_kernel() {
    int which = blockIdx.z;
    const unsigned* Xh = g_xh;
    const unsigned* Zh = g_zhT[which];
    float* Cw = g_qkv[which];

    extern __shared__ unsigned gsm[];
    unsigned sbase = (unsigned)__cvta_generic_to_shared(gsm);
    unsigned sa = sbase, sb = sbase + 2 * GEMM_STAGE * 4;

    int t = threadIdx.x;
    int wid = t >> 5, lane = t & 31;
    int L2 = lane >> 2, L0 = lane & 3;
    int wm = wid >> 1, wn = wid & 1;
    int m0 = blockIdx.x * 128, n0 = blockIdx.y * 128;

    int mat = lane >> 3, lr = lane & 7;
    int a_row = (mat & 1) * 8 + lr;
    int a_kof = (mat >> 1) * 4;
    int b_row = (mat >> 1) * 8 + lr;
    int b_kof = (mat & 1) * 4;

    float acc[2][8][4] = {};

#define G_PREFETCH(kc, sg) do {                                               \
        _Pragma("unroll")                                                     \
        for (int j_ = 0; j_ < 4; j_++) {                                      \
            int u_ = t + j_ * 256;                                            \
            int row_ = u_ >> 3, seg_ = u_ & 7;                                \
            unsigned off_ = (((unsigned)(sg) * 128 + row_) * 36 + seg_ * 4) * 4; \
            cp16(sa + off_, &Xh[(m0 + row_) * (DM/2) + (kc) * 32 + seg_ * 4]); \
            cp16(sb + off_, &Zh[(n0 + row_) * (DM/2) + (kc) * 32 + seg_ * 4]); \
        }                                                                     \
        asm volatile("cp.async.commit_group;");                               \
    } while (0)

    G_PREFETCH(0, 0);

    #pragma unroll 1
    for (int kt = 0; kt < 16; kt++) {
        int st = kt & 1;
        asm volatile("cp.async.wait_group 0;");
        __syncthreads();
        if (kt + 1 < 16) G_PREFETCH(kt + 1, st ^ 1);
        unsigned abase = sa + ((unsigned)(st * 128 + wm * 32 + a_row) * 36 + a_kof) * 4;
        unsigned bbase = sb + ((unsigned)(st * 128 + wn * 64 + b_row) * 36 + b_kof) * 4;
        #pragma unroll
        for (int s8 = 0; s8 < 4; s8++) {
            unsigned a[2][4], b[4][4];
            ldsm4(a[0], abase + (s8 * 8) * 4);
            ldsm4(a[1], abase + (16 * 36 + s8 * 8) * 4);
            #pragma unroll
            for (int p = 0; p < 4; p++)
                ldsm4(b[p], bbase + ((p * 16) * 36 + s8 * 8) * 4);
            #pragma unroll
            for (int p = 0; p < 4; p++) {
                mma16(acc[0][p * 2],     a[0], &b[p][0]);
                mma16(acc[0][p * 2 + 1], a[0], &b[p][2]);
                mma16(acc[1][p * 2],     a[1], &b[p][0]);
                mma16(acc[1][p * 2 + 1], a[1], &b[p][2]);
            }
        }
    }

    // ---- fused Poincare epilogue (scalars from L2-resident globals) ----
    int head = (n0 >> 6) + wn;
    #pragma unroll
    for (int mt = 0; mt < 2; mt++) {
        #pragma unroll
        for (int hh = 0; hh < 2; hh++) {
            int rloc = wm * 32 + mt * 16 + hh * 8 + L2;
            float cx2 = g_rowsq[m0 + rloc];
            float invden = frcp_a(fmaxf(1.0f - cx2, 1e-15f));
            float opc = 1.0f + cx2;
            float sq = 0.f;
            #pragma unroll
            for (int nt = 0; nt < 8; nt++) {
                int cl = wn * 64 + nt * 8 + 2 * L0;
                float4 cs0 = g_cols[which][n0 + cl];
                float4 cs1 = g_cols[which][n0 + cl + 1];
                #pragma unroll
                for (int u = 0; u < 2; u++) {
                    float4 cs = u ? cs1 : cs0;
                    float xz  = acc[mt][nt][hh * 2 + u];
                    float arg = fmaf(xz, cs.x, -opc * cs.z) * invden;
                    float aa  = fabsf(arg);
                    float A   = aa + fsqrt_a(fmaf(aa, aa, 1.0f));
                    float tE  = fex2_a(cs.y * flg2_a(A));
                    float y   = copysignf(0.5f * (tE - frcp_a(tE)), arg);
                    acc[mt][nt][hh * 2 + u] = y;
                    sq = fmaf(y, y, sq);
                }
            }
            sq += __shfl_xor_sync(0xffffffffu, sq, 1);
            sq += __shfl_xor_sync(0xffffffffu, sq, 2);
            float n1  = fmaxf(sqrtf(sq), 1e-15f);
            float s1  = (n1 > MAXN) ? (MAXN / n1) : 1.0f;
            float n1c = n1 * s1;
            float f   = 1.0f / (1.0f + sqrtf(1.0f + n1c * n1c));
            float n2  = fmaxf(n1c * f, 1e-15f);
            float s2v = (n2 > MAXN) ? (MAXN / n2) : 1.0f;
            float hs  = s1 * f * s2v;
            float n3  = n2 * s2v;
            int grow = m0 + rloc;
            if (L0 == 0) g_aux[which][grow * NH + head] = n3 * n3;
            #pragma unroll
            for (int nt = 0; nt < 8; nt++) {
                int cl = wn * 64 + nt * 8 + 2 * L0;
                *(float2*)&Cw[grow * DM + n0 + cl] =
                    make_float2(acc[mt][nt][hh * 2] * hs, acc[mt][nt][hh * 2 + 1] * hs);
            }
        }
    }
}

// ---------------------------------------------------------------------------
// Kernel 2: one-shot fp16 fragment prep for K / gamma*V.
// ---------------------------------------------------------------------------
__global__ __launch_bounds__(256)
void frag_prep_kernel(const float* __restrict__ mask) {
    __shared__ float Ks[64][68];
    __shared__ float Vs[64][68];

    int bh = blockIdx.x, kt = blockIdx.y;
    int b = bh >> 4, h = bh & 15;
    int kj0 = kt * 64;
    int t = threadIdx.x, lane = t & 31;
    int L2 = lane >> 2, L0 = lane & 3;
    int w = t >> 5;
    int s = w & 3;
    bool isV = (w >= 4);

    const float* K = g_qkv[1];
    const float* V = g_qkv[2];

    #pragma unroll
    for (int j = 0; j < 4; j++) {
        int idx = t + j * 256;
        int row = idx >> 4, c4 = (idx & 15) * 4;
        int gr = b * SS + kj0 + row;
        *(float4*)&Ks[row][c4] = *(const float4*)&K[gr * DM + h * DH + c4];
        float v2 = g_aux[2][gr * NH + h];
        float gam = 2.0f * frcp_a(fmaxf(1.0f - v2, 1e-15f));
        float4 vv = *(const float4*)&V[gr * DM + h * DH + c4];
        *(float4*)&Vs[row][c4] = make_float4(vv.x * gam, vv.y * gam, vv.z * gam, vv.w * gam);
    }
    if (t < 64) {
        int gr = b * SS + kj0 + t;
        float k2 = g_aux[1][gr * NH + h];
        float v2 = g_aux[2][gr * NH + h];
        g_sck[bh * 1024 + kj0 + t] =
            make_float4(k2, frcp_a(fmaxf(1.0f - k2, 1e-15f)),
                        2.0f * frcp_a(fmaxf(1.0f - v2, 1e-15f)) - 1.0f,
                        __expf(mask[b * SS + kj0 + t]));
    }
    __syncthreads();

    unsigned wf[16];
    if (!isV) {
        #pragma unroll
        for (int nt = 0; nt < 8; nt++) {
            int c = nt * 8 + L2;
            wf[2*nt]   = packh2(Ks[c][s * 16 + 2 * L0],     Ks[c][s * 16 + 2 * L0 + 1]);
            wf[2*nt+1] = packh2(Ks[c][s * 16 + 2 * L0 + 8], Ks[c][s * 16 + 2 * L0 + 9]);
        }
    } else {
        #pragma unroll
        for (int nt = 0; nt < 8; nt++) {
            int d = nt * 8 + L2;
            wf[2*nt]   = packh2(Vs[s * 16 + 2 * L0][d],     Vs[s * 16 + 2 * L0 + 1][d]);
            wf[2*nt+1] = packh2(Vs[s * 16 + 2 * L0 + 8][d], Vs[s * 16 + 2 * L0 + 9][d]);
        }
    }
    unsigned base = (((unsigned)(bh * 16 + kt) * 4) + s) * 512 + lane * 4;
    unsigned* dst = isV ? g_vfrag : g_kfrag;
    #pragma unroll
    for (int i4 = 0; i4 < 4; i4++)
        *(uint4*)&dst[base + i4 * 128] = ((uint4*)wf)[i4];
}

// ---------------------------------------------------------------------------
// Kernel 3: flash-style hyperbolic attention, fp16 m16n8k16.
// P stays in registers: the PV A-fragment is thread-local (thread (L2,L0)
// produces exactly the w-columns {st*16+2L0, +1} and {st*16+8+2L0, +1} it
// consumes), so the ps smem round-trip is deleted.
// ---------------------------------------------------------------------------
#define ATT_SMEM_WORDS (4096 + 8*64*4 + 128)
__global__ __launch_bounds__(256, 2)
void attn_kernel(float* __restrict__ out) {
    extern __shared__ unsigned smu[];
    unsigned* qf = smu;                                   // 4096: Q fp16 frags
    float4* sws = (float4*)(smu + 4096);                  // per-warp 64 float4
    float* q2s  = (float*)(smu + 4096 + 8*64*4);

    int bh = blockIdx.x, qt = blockIdx.y;
    int b = bh >> 4, h = bh & 15;
    int t = threadIdx.x, wid = t >> 5, lane = t & 31;
    int L2 = lane >> 2, L0 = lane & 3;
    int qi0 = qt * 128;

    const float* Q = g_qkv[0];

    #pragma unroll
    for (int j = 0; j < 8; j++) {
        int idx = t + j * 256;
        int row = idx >> 4, c4 = (idx & 15) * 4;
        float4 v = *(const float4*)&Q[(b * SS + qi0 + row) * DM + h * DH + c4];
        int rb = row >> 4, rr = row & 15;
        int s  = c4 >> 4;
        int j0 = (c4 & 15) >> 1;
        int lane0 = (rr & 7) * 4 + (j0 & 3);
        int reg   = (rr >> 3) + 2 * (j0 >> 2);
        unsigned* qb = qf + (((rb * 4 + s) * 32 + lane0) * 4) + reg;
        qb[0] = packh2(v.x, v.y);
        qb[4] = packh2(v.z, v.w);
    }
    if (t < 128) q2s[t] = g_aux[0][(b * SS + qi0 + t) * NH + h];
    __syncthreads();

    int rA = wid * 16 + L2;
    float q2_0 = q2s[rA], q2_1 = q2s[rA + 8];
    float tiq0 = 2.0f * frcp_a(fmaxf(1.0f - q2_0, 1e-15f));
    float tiq1 = 2.0f * frcp_a(fmaxf(1.0f - q2_1, 1e-15f));

    float4* swsW = sws + wid * 64;
    const float4* sckB = g_sck + bh * 1024;

    float o[8][4] = {};
    float accd0 = 0.f, accd1 = 0.f;

    for (int kt = 0; kt < SS / 64; kt++) {
        int kj0 = kt * 64;
        size_t fb = (size_t)((unsigned)(bh * 16 + kt) * 4) * 512 + lane * 4;
        const unsigned* kfb = g_kfrag + fb;
        const unsigned* vfb = g_vfrag + fb;

        swsW[lane * 2]     = sckB[kj0 + lane * 2];
        swsW[lane * 2 + 1] = sckB[kj0 + lane * 2 + 1];
        __syncwarp();

        // ---- QK^T: 4 k16-steps ----
        float s[8][4] = {};
        #pragma unroll
        for (int st = 0; st < 4; st++) {
            uint4 af = *(uint4*)&qf[((wid * 4 + st) * 32 + lane) * 4];
            unsigned a[4] = { af.x, af.y, af.z, af.w };
            unsigned kw[16];
            #pragma unroll
            for (int i4 = 0; i4 < 4; i4++)
                *(uint4*)&kw[i4 * 4] = *(const uint4*)&kfb[st * 512 + i4 * 128];
            #pragma unroll
            for (int nt = 0; nt < 8; nt++) mma16(s[nt], a, &kw[nt * 2]);
        }

        // ---- score -> weight (registers only), accumulate denominator ----
        unsigned pwA[8], pwB[8];        // packed P rows rA / rA+8, per nt
        #pragma unroll
        for (int nt = 0; nt < 8; nt++) {
            int j0 = nt * 8 + 2 * L0;
            float4 c0 = swsW[j0], c1 = swsW[j0 + 1];
            float w[4];
            #pragma unroll
            for (int e = 0; e < 4; e++) {
                float q2v = (e < 2) ? q2_0 : q2_1;
                float cc  = ((e < 2) ? tiq0 : tiq1) * ((e & 1) ? c1.y : c0.y);
                float k2v = (e & 1) ? c1.x : c0.x;
                float emv = (e & 1) ? c1.w : c0.w;
                float num = fmaxf(fmaf(-2.0f, s[nt][e], q2v + k2v), 1e-15f);
                float tt  = num * cc;
                float sr  = fsqrt_a(tt * (tt + 2.0f));
                w[e] = __fdividef(emv, (1.0f + tt) + sr);
            }
            accd0 = fmaf(w[0], c0.z, fmaf(w[1], c1.z, accd0));
            accd1 = fmaf(w[2], c0.z, fmaf(w[3], c1.z, accd1));
            pwA[nt] = packh2(w[0], w[1]);
            pwB[nt] = packh2(w[2], w[3]);
        }

        // ---- P @ (gamma V): A-fragment直接 from registers ----
        #pragma unroll
        for (int st = 0; st < 4; st++) {
            unsigned a[4] = { pwA[2 * st], pwB[2 * st], pwA[2 * st + 1], pwB[2 * st + 1] };
            unsigned vw[16];
            #pragma unroll
            for (int i4 = 0; i4 < 4; i4++)
                *(uint4*)&vw[i4 * 4] = *(const uint4*)&vfb[st * 512 + i4 * 128];
            #pragma unroll
            for (int nt = 0; nt < 8; nt++) mma16(o[nt], a, &vw[nt * 2]);
        }
        __syncwarp();
    }

    accd0 += __shfl_xor_sync(0xffffffffu, accd0, 1);
    accd0 += __shfl_xor_sync(0xffffffffu, accd0, 2);
    accd1 += __shfl_xor_sync(0xffffffffu, accd1, 1);
    accd1 += __shfl_xor_sync(0xffffffffu, accd1, 2);
    #pragma unroll
    for (int rh = 0; rh < 2; rh++) {
        float accd = rh ? accd1 : accd0;
        float invd = 1.0f / fmaxf(accd, 1e-10f);
        float tm[8][2];
        float sq = 0.f;
        #pragma unroll
        for (int nt = 0; nt < 8; nt++) {
            tm[nt][0] = o[nt][rh * 2 + 0] * invd;
            tm[nt][1] = o[nt][rh * 2 + 1] * invd;
            sq += tm[nt][0] * tm[nt][0] + tm[nt][1] * tm[nt][1];
        }
        sq += __shfl_xor_sync(0xffffffffu, sq, 1);
        sq += __shfl_xor_sync(0xffffffffu, sq, 2);
        float f = 1.0f / (1.0f + sqrtf(fmaxf(1.0f - sq, 1e-15f)));
        float n = fmaxf(sqrtf(sq) * f, 1e-15f);
        float s2 = (n > MAXN) ? (MAXN / n) : 1.0f;
        float g = f * s2;
        int qrow = qi0 + rA + rh * 8;
        #pragma unroll
        for (int nt = 0; nt < 8; nt++) {
            *(float2*)&out[(b * SS + qrow) * DM + h * DH + nt * 8 + 2 * L0] =
                make_float2(tm[nt][0] * g, tm[nt][1] * g);
        }
    }
}

// ---------------------------------------------------------------------------
extern "C" void kernel_launch(void* const* d_in, const int* in_sizes, int n_in,
                              void* d_out, int out_size) {
    const float* hidden = (const float*)d_in[0];
    const float* amask  = (const float*)d_in[1];
    const float* qz = (const float*)d_in[2];
    const float* qr = (const float*)d_in[3];
    const float* kz = (const float*)d_in[4];
    const float* kr = (const float*)d_in[5];
    const float* vz = (const float*)d_in[6];
    const float* vr = (const float*)d_in[7];
    float* out = (float*)d_out;

    static bool attr_done = false;
    if (!attr_done) {
        cudaFuncSetAttribute(attn_kernel, cudaFuncAttributeMaxDynamicSharedMemorySize,
                             ATT_SMEM_WORDS * 4);
        cudaFuncSetAttribute(gemm_proj_kernel, cudaFuncAttributeMaxDynamicSharedMemorySize,
                             GEMM_SMEM_WORDS * 4);
        attr_done = true;
    }

    xcvt_kernel<<<256, 256>>>(hidden);
    ztrans_kernel<<<dim3(16, 16, 3), 256>>>(qz, kz, vz);
    col_finish_kernel<<<12, 256>>>(qr, kr, vr);
    gemm_proj_kernel<<<dim3(MROWS / 128, DM / 128, 3), 256, GEMM_SMEM_WORDS * 4>>>();
    frag_prep_kernel<<<dim3(32, 16), 256>>>(amask);
    attn_kernel<<<dim3(BB * NH, SS / 128), 256, ATT_SMEM_WORDS * 4>>>(out);
}

// round 17
// speedup vs baseline: 1.2293x; 1.0347x over previous
#include <cuda_runtime.h>
#include <cuda_fp16.h>
#include <math.h>

#define BB 2
#define SS 1024
#define DM 1024
#define NH 16
#define DH 64
#define MROWS (BB*SS)
#define MAXN 0.996f

__device__ float g_aux[3][MROWS*NH];        // per-(row,head) final ||y||^2
__device__ unsigned g_qfrag[32*64*4*128];   // Q  fp16 mma-frag order (4MB)
__device__ unsigned g_kfrag[32*16*4*512];   // K  fp16 mma-frag order (4MB)
__device__ unsigned g_vfrag[32*16*4*512];   // gamma*V fp16 frag order (4MB)
__device__ float4   g_sck[32*1024];         // per (bh,key): {k2, 1/(1-k2), gm1, e^mask}
__device__ unsigned g_xh[MROWS*DM/2];       // fp16x2(X)   [m][k/2]
__device__ unsigned g_zhT[3][DM*DM/2];      // fp16x2(Z^T) [n][k/2]
__device__ float    g_rowsq[MROWS];         // ||x_row||^2
__device__ float    g_colpart[3][16][DM];   // per-ktile col-norm partials
__device__ float4   g_cols[3][DM];          // {2cosh(2r)/zn, 2zn, sinh(2r), 0}

__device__ __forceinline__ unsigned packh2(float lo, float hi) {
    __half2 h = __floats2half2_rn(lo, hi);
    return *(unsigned*)&h;
}
__device__ __forceinline__ void mma16(float* d, const unsigned* a, const unsigned* b) {
    asm volatile("mma.sync.aligned.m16n8k16.row.col.f32.f16.f16.f32 "
        "{%0,%1,%2,%3}, {%4,%5,%6,%7}, {%8,%9}, {%0,%1,%2,%3};"
        : "+f"(d[0]), "+f"(d[1]), "+f"(d[2]), "+f"(d[3])
        : "r"(a[0]), "r"(a[1]), "r"(a[2]), "r"(a[3]), "r"(b[0]), "r"(b[1]));
}
__device__ __forceinline__ void ldsm4(unsigned* r, unsigned addr) {
    asm volatile("ldmatrix.sync.aligned.m8n8.x4.shared.b16 {%0,%1,%2,%3}, [%4];"
        : "=r"(r[0]), "=r"(r[1]), "=r"(r[2]), "=r"(r[3]) : "r"(addr));
}
__device__ __forceinline__ float fsqrt_a(float x){float r;asm("sqrt.approx.f32 %0,%1;":"=f"(r):"f"(x));return r;}
__device__ __forceinline__ float frcp_a (float x){float r;asm("rcp.approx.f32 %0,%1;" :"=f"(r):"f"(x));return r;}
__device__ __forceinline__ float flg2_a (float x){float r;asm("lg2.approx.f32 %0,%1;" :"=f"(r):"f"(x));return r;}
__device__ __forceinline__ float fex2_a (float x){float r;asm("ex2.approx.f32 %0,%1;" :"=f"(r):"f"(x));return r;}
__device__ __forceinline__ void cp16(unsigned s, const void* g) {
    asm volatile("cp.async.ca.shared.global [%0], [%1], 16;" :: "r"(s), "l"(g));
}

// ---------------------------------------------------------------------------
// Kernel 0a: X -> fp16 + row norms
// ---------------------------------------------------------------------------
__global__ __launch_bounds__(256)
void xcvt_kernel(const float* __restrict__ X) {
    int row = blockIdx.x * 8 + (threadIdx.x >> 5), lane = threadIdx.x & 31;
    const float* xr = X + row * DM;
    unsigned* xo = g_xh + row * (DM / 2);
    float s = 0.f;
    #pragma unroll
    for (int i = 0; i < 8; i++) {
        float4 v = *(const float4*)&xr[(i * 32 + lane) * 4];
        s = fmaf(v.x, v.x, fmaf(v.y, v.y, fmaf(v.z, v.z, fmaf(v.w, v.w, s))));
        *(uint2*)&xo[(i * 32 + lane) * 2] = make_uint2(packh2(v.x, v.y), packh2(v.z, v.w));
    }
    #pragma unroll
    for (int off = 16; off > 0; off >>= 1) s += __shfl_xor_sync(0xffffffffu, s, off);
    if (lane == 0) g_rowsq[row] = s;
}

// ---------------------------------------------------------------------------
// Kernel 0b: Z -> fp16 TRANSPOSED ([n][k]) via 64x64 smem tiles + col partials
// ---------------------------------------------------------------------------
__global__ __launch_bounds__(256)
void ztrans_kernel(const float* __restrict__ qz, const float* __restrict__ kz,
                   const float* __restrict__ vz) {
    __shared__ float tile[64][65];
    __shared__ float redc[16][64];
    int which = blockIdx.z;
    int k0 = blockIdx.x * 64, n0 = blockIdx.y * 64;
    const float* Z = (which == 0) ? qz : (which == 1) ? kz : vz;
    int t = threadIdx.x;
    float cp0 = 0.f, cp1 = 0.f, cp2 = 0.f, cp3 = 0.f;
    #pragma unroll
    for (int j = 0; j < 4; j++) {
        int idx = t + j * 256;
        int r = idx >> 4, c4 = (idx & 15) * 4;
        float4 v = *(const float4*)&Z[(k0 + r) * DM + n0 + c4];
        tile[r][c4] = v.x; tile[r][c4 + 1] = v.y;
        tile[r][c4 + 2] = v.z; tile[r][c4 + 3] = v.w;
        cp0 = fmaf(v.x, v.x, cp0); cp1 = fmaf(v.y, v.y, cp1);
        cp2 = fmaf(v.z, v.z, cp2); cp3 = fmaf(v.w, v.w, cp3);
    }
    int cg = (t & 15) * 4;
    redc[t >> 4][cg] = cp0; redc[t >> 4][cg + 1] = cp1;
    redc[t >> 4][cg + 2] = cp2; redc[t >> 4][cg + 3] = cp3;
    __syncthreads();
    if (t < 64) {
        float s = 0.f;
        #pragma unroll
        for (int g = 0; g < 16; g++) s += redc[g][t];
        g_colpart[which][blockIdx.x][n0 + t] = s;
    }
    #pragma unroll
    for (int j = 0; j < 4; j++) {
        int idx = t + j * 256;
        int nr = idx >> 4, kc4 = (idx & 15) * 4;
        *(uint2*)&g_zhT[which][(n0 + nr) * (DM / 2) + (k0 + kc4) / 2] =
            make_uint2(packh2(tile[kc4][nr], tile[kc4 + 1][nr]),
                       packh2(tile[kc4 + 2][nr], tile[kc4 + 3][nr]));
    }
}

// ---------------------------------------------------------------------------
// Kernel 0c: finish column scalars (sum 16 partials)
// ---------------------------------------------------------------------------
__global__ __launch_bounds__(256)
void col_finish_kernel(const float* __restrict__ qr, const float* __restrict__ kr,
                       const float* __restrict__ vr) {
    int gid = blockIdx.x * 256 + threadIdx.x;   // 0..3071
    int which = gid >> 10, col = gid & 1023;
    const float* R = (which == 0) ? qr : (which == 1) ? kr : vr;
    float zs = 0.f;
    #pragma unroll
    for (int p = 0; p < 16; p++) zs += g_colpart[which][p][col];
    float zn = fmaxf(fsqrt_a(zs), 1e-15f);
    float rv = 2.0f * R[col];
    float e  = fex2_a(rv * 1.44269504f);
    float ie = frcp_a(e);
    g_cols[which][col] = make_float4((e + ie) * frcp_a(zn), 2.0f * zn, 0.5f * (e - ie), 0.f);
}

// ---------------------------------------------------------------------------
// Kernel 1: fp16 m16n8k16 GEMM (R13 mainloop) + fused Poincare epilogue that
// emits mma FRAGMENTS directly (Q/K/gammaV) via fp16 smem staging.
// Block tile 128x128 = {2 key-tiles or 8 q16-tiles} x {2 complete heads}.
// ---------------------------------------------------------------------------
#define GEMM_STAGE (128*36)                    // uints per stage per operand
#define GEMM_SMEM_WORDS (4*GEMM_STAGE)
__global__ __launch_bounds__(256, 2)
void gemm_proj_kernel() {
    int which = blockIdx.z;
    const unsigned* Xh = g_xh;
    const unsigned* Zh = g_zhT[which];

    extern __shared__ unsigned gsm[];
    unsigned sbase = (unsigned)__cvta_generic_to_shared(gsm);
    unsigned sa = sbase, sb = sbase + 2 * GEMM_STAGE * 4;

    int t = threadIdx.x;
    int wid = t >> 5, lane = t & 31;
    int L2 = lane >> 2, L0 = lane & 3;
    int wm = wid >> 1, wn = wid & 1;
    int m0 = blockIdx.x * 128, n0 = blockIdx.y * 128;

    int mat = lane >> 3, lr = lane & 7;
    int a_row = (mat & 1) * 8 + lr;
    int a_kof = (mat >> 1) * 4;
    int b_row = (mat >> 1) * 8 + lr;
    int b_kof = (mat & 1) * 4;

    float acc[2][8][4] = {};

#define G_PREFETCH(kc, sg) do {                                               \
        _Pragma("unroll")                                                     \
        for (int j_ = 0; j_ < 4; j_++) {                                      \
            int u_ = t + j_ * 256;                                            \
            int row_ = u_ >> 3, seg_ = u_ & 7;                                \
            unsigned off_ = (((unsigned)(sg) * 128 + row_) * 36 + seg_ * 4) * 4; \
            cp16(sa + off_, &Xh[(m0 + row_) * (DM/2) + (kc) * 32 + seg_ * 4]); \
            cp16(sb + off_, &Zh[(n0 + row_) * (DM/2) + (kc) * 32 + seg_ * 4]); \
        }                                                                     \
        asm volatile("cp.async.commit_group;");                               \
    } while (0)

    G_PREFETCH(0, 0);

    #pragma unroll 1
    for (int kt = 0; kt < 16; kt++) {
        int st = kt & 1;
        asm volatile("cp.async.wait_group 0;");
        __syncthreads();
        if (kt + 1 < 16) G_PREFETCH(kt + 1, st ^ 1);
        unsigned abase = sa + ((unsigned)(st * 128 + wm * 32 + a_row) * 36 + a_kof) * 4;
        unsigned bbase = sb + ((unsigned)(st * 128 + wn * 64 + b_row) * 36 + b_kof) * 4;
        #pragma unroll
        for (int s8 = 0; s8 < 4; s8++) {
            unsigned a[2][4], b[4][4];
            ldsm4(a[0], abase + (s8 * 8) * 4);
            ldsm4(a[1], abase + (16 * 36 + s8 * 8) * 4);
            #pragma unroll
            for (int p = 0; p < 4; p++)
                ldsm4(b[p], bbase + ((p * 16) * 36 + s8 * 8) * 4);
            #pragma unroll
            for (int p = 0; p < 4; p++) {
                mma16(acc[0][p * 2],     a[0], &b[p][0]);
                mma16(acc[0][p * 2 + 1], a[0], &b[p][2]);
                mma16(acc[1][p * 2],     a[1], &b[p][0]);
                mma16(acc[1][p * 2 + 1], a[1], &b[p][2]);
            }
        }
    }
    __syncthreads();   // all smem operand reads done: safe to reuse as staging

    // ---- Poincare epilogue -> packed fp16 tile in smem  Su[128][68] ----
    unsigned (*Su)[68] = (unsigned(*)[68])gsm;
    int head = (n0 >> 6) + wn;
    #pragma unroll
    for (int mt = 0; mt < 2; mt++) {
        #pragma unroll
        for (int hh = 0; hh < 2; hh++) {
            int rloc = wm * 32 + mt * 16 + hh * 8 + L2;
            float cx2 = g_rowsq[m0 + rloc];
            float invden = frcp_a(fmaxf(1.0f - cx2, 1e-15f));
            float opc = 1.0f + cx2;
            float sq = 0.f;
            #pragma unroll
            for (int nt = 0; nt < 8; nt++) {
                int cl = wn * 64 + nt * 8 + 2 * L0;
                float4 cs0 = g_cols[which][n0 + cl];
                float4 cs1 = g_cols[which][n0 + cl + 1];
                #pragma unroll
                for (int u = 0; u < 2; u++) {
                    float4 cs = u ? cs1 : cs0;
                    float xz  = acc[mt][nt][hh * 2 + u];
                    float arg = fmaf(xz, cs.x, -opc * cs.z) * invden;
                    float aa  = fabsf(arg);
                    float A   = aa + fsqrt_a(fmaf(aa, aa, 1.0f));
                    float tE  = fex2_a(cs.y * flg2_a(A));
                    float y   = copysignf(0.5f * (tE - frcp_a(tE)), arg);
                    acc[mt][nt][hh * 2 + u] = y;
                    sq = fmaf(y, y, sq);
                }
            }
            sq += __shfl_xor_sync(0xffffffffu, sq, 1);
            sq += __shfl_xor_sync(0xffffffffu, sq, 2);
            float n1  = fmaxf(sqrtf(sq), 1e-15f);
            float s1  = (n1 > MAXN) ? (MAXN / n1) : 1.0f;
            float n1c = n1 * s1;
            float f   = 1.0f / (1.0f + sqrtf(1.0f + n1c * n1c));
            float n2  = fmaxf(n1c * f, 1e-15f);
            float s2v = (n2 > MAXN) ? (MAXN / n2) : 1.0f;
            float hs  = s1 * f * s2v;
            float n3  = n2 * s2v;
            if (L0 == 0) g_aux[which][(m0 + rloc) * NH + head] = n3 * n3;
            float gam = (which == 2) ? 2.0f * frcp_a(fmaxf(1.0f - n3 * n3, 1e-15f)) : 1.0f;
            float hsg = hs * gam;
            #pragma unroll
            for (int nt = 0; nt < 8; nt++)
                Su[rloc][wn * 32 + nt * 4 + L0] =
                    packh2(acc[mt][nt][hh * 2] * hsg, acc[mt][nt][hh * 2 + 1] * hsg);
        }
    }
    __syncthreads();

    // ---- fragment extraction + coalesced STG ----
    int b_ = m0 >> 10;
    int mloc = m0 & 1023;
    if (which == 0) {
        #pragma unroll
        for (int i = 0; i < 8; i++) {
            int tk = wid * 8 + i;          // 64 tasks: (rb, hh, s)
            int rb = tk >> 3;
            int s  = tk & 3;
            int hh = (tk >> 2) & 1;
            int hg = (n0 >> 6) + hh;
            int cb = hh * 32 + s * 8 + L0;
            int r0 = rb * 16 + L2;
            uint4 v;
            v.x = Su[r0][cb];     v.y = Su[r0 + 8][cb];
            v.z = Su[r0][cb + 4]; v.w = Su[r0 + 8][cb + 4];
            size_t dst = ((((size_t)(b_ * 16 + hg) * 64 + (mloc >> 4) + rb) * 4 + s) * 32 + lane) * 4;
            *(uint4*)&g_qfrag[dst] = v;
        }
    } else {
        unsigned* dstArr = (which == 1) ? g_kfrag : g_vfrag;
        #pragma unroll
        for (int i = 0; i < 2; i++) {
            int tk = wid * 2 + i;          // 16 tasks: (ktl, hh, s)
            int s   = tk & 3;
            int hh  = (tk >> 2) & 1;
            int ktl = tk >> 3;
            int hg  = (n0 >> 6) + hh;
            int bhI = b_ * 16 + hg;
            int ktg = (mloc >> 6) + ktl;
            unsigned wf[16];
            if (which == 1) {
                #pragma unroll
                for (int nt = 0; nt < 8; nt++) {
                    int r = ktl * 64 + nt * 8 + L2;
                    wf[2*nt]   = Su[r][hh * 32 + s * 8 + L0];
                    wf[2*nt+1] = Su[r][hh * 32 + s * 8 + L0 + 4];
                }
            } else {
                const __half* hS = (const __half*)gsm;       // row stride 136 halves
                #pragma unroll
                for (int nt = 0; nt < 8; nt++) {
                    int d  = hh * 64 + nt * 8 + L2;
                    int r0 = ktl * 64 + s * 16 + 2 * L0;
                    __half2 lo = __halves2half2(hS[r0 * 136 + d],       hS[(r0 + 1) * 136 + d]);
                    __half2 hi = __halves2half2(hS[(r0 + 8) * 136 + d], hS[(r0 + 9) * 136 + d]);
                    wf[2*nt]   = *(unsigned*)&lo;
                    wf[2*nt+1] = *(unsigned*)&hi;
                }
            }
            unsigned base = (((unsigned)(bhI * 16 + ktg) * 4) + s) * 512 + lane * 4;
            #pragma unroll
            for (int i4 = 0; i4 < 4; i4++)
                *(uint4*)&dstArr[base + i4 * 128] = ((uint4*)wf)[i4];
        }
    }
}

// ---------------------------------------------------------------------------
// Kernel 2: per-key scalar prep {k2, 1/(1-k2), gamma_v-1, e^mask}
// ---------------------------------------------------------------------------
__global__ __launch_bounds__(256)
void sck_prep_kernel(const float* __restrict__ mask) {
    int gid = blockIdx.x * 256 + threadIdx.x;   // 0..32767
    int bh = gid >> 10, key = gid & 1023;
    int b = bh >> 4, h = bh & 15;
    float k2 = g_aux[1][(b * SS + key) * NH + h];
    float v2 = g_aux[2][(b * SS + key) * NH + h];
    g_sck[gid] = make_float4(k2, frcp_a(fmaxf(1.0f - k2, 1e-15f)),
                             2.0f * frcp_a(fmaxf(1.0f - v2, 1e-15f)) - 1.0f,
                             __expf(mask[b * SS + key]));
}

// ---------------------------------------------------------------------------
// Kernel 3: flash-style hyperbolic attention; all operands pre-fragmented.
// Q frags hoisted to registers; P stays in registers (R16).
// ---------------------------------------------------------------------------
#define ATT_SMEM_WORDS (8*64*4 + 128)
__global__ __launch_bounds__(256, 2)
void attn_kernel(float* __restrict__ out) {
    extern __shared__ unsigned smu[];
    float4* sws = (float4*)smu;                  // per-warp 64 float4
    float* q2s  = (float*)(smu + 8*64*4);

    int bh = blockIdx.x, qt = blockIdx.y;
    int b = bh >> 4, h = bh & 15;
    int t = threadIdx.x, wid = t >> 5, lane = t & 31;
    int L2 = lane >> 2, L0 = lane & 3;
    int qi0 = qt * 128;

    if (t < 128) q2s[t] = g_aux[0][(b * SS + qi0 + t) * NH + h];
    __syncthreads();

    // Q fragments for this warp's 16 rows: 4 steps x uint4 (register-resident)
    uint4 af4[4];
    #pragma unroll
    for (int st = 0; st < 4; st++)
        af4[st] = *(const uint4*)&g_qfrag[
            ((((size_t)bh * 64 + (qi0 >> 4) + wid) * 4 + st) * 32 + lane) * 4];

    int rA = wid * 16 + L2;
    float q2_0 = q2s[rA], q2_1 = q2s[rA + 8];
    float tiq0 = 2.0f * frcp_a(fmaxf(1.0f - q2_0, 1e-15f));
    float tiq1 = 2.0f * frcp_a(fmaxf(1.0f - q2_1, 1e-15f));

    float4* swsW = sws + wid * 64;
    const float4* sckB = g_sck + bh * 1024;

    float o[8][4] = {};
    float accd0 = 0.f, accd1 = 0.f;

    for (int kt = 0; kt < SS / 64; kt++) {
        int kj0 = kt * 64;
        size_t fb = (size_t)((unsigned)(bh * 16 + kt) * 4) * 512 + lane * 4;
        const unsigned* kfb = g_kfrag + fb;
        const unsigned* vfb = g_vfrag + fb;

        swsW[lane * 2]     = sckB[kj0 + lane * 2];
        swsW[lane * 2 + 1] = sckB[kj0 + lane * 2 + 1];
        __syncwarp();

        // ---- QK^T: 4 k16-steps ----
        float s[8][4] = {};
        #pragma unroll
        for (int st = 0; st < 4; st++) {
            unsigned a[4] = { af4[st].x, af4[st].y, af4[st].z, af4[st].w };
            unsigned kw[16];
            #pragma unroll
            for (int i4 = 0; i4 < 4; i4++)
                *(uint4*)&kw[i4 * 4] = *(const uint4*)&kfb[st * 512 + i4 * 128];
            #pragma unroll
            for (int nt = 0; nt < 8; nt++) mma16(s[nt], a, &kw[nt * 2]);
        }

        // ---- score -> weight (registers only), accumulate denominator ----
        unsigned pwA[8], pwB[8];
        #pragma unroll
        for (int nt = 0; nt < 8; nt++) {
            int j0 = nt * 8 + 2 * L0;
            float4 c0 = swsW[j0], c1 = swsW[j0 + 1];
            float w[4];
            #pragma unroll
            for (int e = 0; e < 4; e++) {
                float q2v = (e < 2) ? q2_0 : q2_1;
                float cc  = ((e < 2) ? tiq0 : tiq1) * ((e & 1) ? c1.y : c0.y);
                float k2v = (e & 1) ? c1.x : c0.x;
                float emv = (e & 1) ? c1.w : c0.w;
                float num = fmaxf(fmaf(-2.0f, s[nt][e], q2v + k2v), 1e-15f);
                float tt  = num * cc;
                float sr  = fsqrt_a(tt * (tt + 2.0f));
                w[e] = __fdividef(emv, (1.0f + tt) + sr);
            }
            accd0 = fmaf(w[0], c0.z, fmaf(w[1], c1.z, accd0));
            accd1 = fmaf(w[2], c0.z, fmaf(w[3], c1.z, accd1));
            pwA[nt] = packh2(w[0], w[1]);
            pwB[nt] = packh2(w[2], w[3]);
        }

        // ---- P @ (gamma V): A-fragment from registers ----
        #pragma unroll
        for (int st = 0; st < 4; st++) {
            unsigned a[4] = { pwA[2 * st], pwB[2 * st], pwA[2 * st + 1], pwB[2 * st + 1] };
            unsigned vw[16];
            #pragma unroll
            for (int i4 = 0; i4 < 4; i4++)
                *(uint4*)&vw[i4 * 4] = *(const uint4*)&vfb[st * 512 + i4 * 128];
            #pragma unroll
            for (int nt = 0; nt < 8; nt++) mma16(o[nt], a, &vw[nt * 2]);
        }
        __syncwarp();
    }

    accd0 += __shfl_xor_sync(0xffffffffu, accd0, 1);
    accd0 += __shfl_xor_sync(0xffffffffu, accd0, 2);
    accd1 += __shfl_xor_sync(0xffffffffu, accd1, 1);
    accd1 += __shfl_xor_sync(0xffffffffu, accd1, 2);
    #pragma unroll
    for (int rh = 0; rh < 2; rh++) {
        float accd = rh ? accd1 : accd0;
        float invd = 1.0f / fmaxf(accd, 1e-10f);
        float tm[8][2];
        float sq = 0.f;
        #pragma unroll
        for (int nt = 0; nt < 8; nt++) {
            tm[nt][0] = o[nt][rh * 2 + 0] * invd;
            tm[nt][1] = o[nt][rh * 2 + 1] * invd;
            sq += tm[nt][0] * tm[nt][0] + tm[nt][1] * tm[nt][1];
        }
        sq += __shfl_xor_sync(0xffffffffu, sq, 1);
        sq += __shfl_xor_sync(0xffffffffu, sq, 2);
        float f = 1.0f / (1.0f + sqrtf(fmaxf(1.0f - sq, 1e-15f)));
        float n = fmaxf(sqrtf(sq) * f, 1e-15f);
        float s2 = (n > MAXN) ? (MAXN / n) : 1.0f;
        float g = f * s2;
        int qrow = qi0 + rA + rh * 8;
        #pragma unroll
        for (int nt = 0; nt < 8; nt++) {
            *(float2*)&out[(b * SS + qrow) * DM + h * DH + nt * 8 + 2 * L0] =
                make_float2(tm[nt][0] * g, tm[nt][1] * g);
        }
    }
}

// ---------------------------------------------------------------------------
extern "C" void kernel_launch(void* const* d_in, const int* in_sizes, int n_in,
                              void* d_out, int out_size) {
    const float* hidden = (const float*)d_in[0];
    const float* amask  = (const float*)d_in[1];
    const float* qz = (const float*)d_in[2];
    const float* qr = (const float*)d_in[3];
    const float* kz = (const float*)d_in[4];
    const float* kr = (const float*)d_in[5];
    const float* vz = (const float*)d_in[6];
    const float* vr = (const float*)d_in[7];
    float* out = (float*)d_out;

    static bool attr_done = false;
    if (!attr_done) {
        cudaFuncSetAttribute(attn_kernel, cudaFuncAttributeMaxDynamicSharedMemorySize,
                             ATT_SMEM_WORDS * 4);
        cudaFuncSetAttribute(gemm_proj_kernel, cudaFuncAttributeMaxDynamicSharedMemorySize,
                             GEMM_SMEM_WORDS * 4);
        attr_done = true;
    }

    xcvt_kernel<<<256, 256>>>(hidden);
    ztrans_kernel<<<dim3(16, 16, 3), 256>>>(qz, kz, vz);
    col_finish_kernel<<<12, 256>>>(qr, kr, vr);
    gemm_proj_kernel<<<dim3(MROWS / 128, DM / 128, 3), 256, GEMM_SMEM_WORDS * 4>>>();
    sck_prep_kernel<<<128, 256>>>(amask);
    attn_kernel<<<dim3(BB * NH, SS / 128), 256, ATT_SMEM_WORDS * 4>>>(out);
}